// round 15
// baseline (speedup 1.0000x reference)
#include <cuda_runtime.h>

#define LROW 16384
#define N1 8199
#define N2 4107
#define N3 2061
#define N4 1038
#define ROWS_MAX 2048

#define S1 8200
#define S2 4112
#define S3 2064
#define S4 1040

__device__ float g_d1[(size_t)ROWS_MAX * S1];
__device__ float g_d2[(size_t)ROWS_MAX * S2];
__device__ float g_d3[(size_t)ROWS_MAX * S3];
__device__ float g_d4[(size_t)ROWS_MAX * S4];
__device__ float g_a4[(size_t)ROWS_MAX * S4];
__device__ float g_thr[ROWS_MAX];

// smem: fwd: A1[0,8208) A2[8208,12320), XW[12320,14688) warp staging; A3 overlays A1.
//       inv: REC[0,8208) R3[8208,12320), R4 overlays REC.
#define SM_FLOATS_FWD 14688
#define SM_BYTES_FWD  (SM_FLOATS_FWD * 4)
#define SM_FLOATS_INV 12320
#define SM_BYTES_INV  (SM_FLOATS_INV * 4)
#define OFF_HI  8208
#define OFF_XW  12320
#define XW_STRIDE 296

#define HLIT { \
    0.05441584224308161f,    0.3128715909144659f,    0.6756307362980128f, \
    0.5853546836548691f,    -0.015829105256023893f, -0.2840155429624281f, \
    0.00047248457399797254f, 0.128747426620186f,    -0.01736930100202211f, \
   -0.04408825393106472f,    0.013981027917015516f,  0.008746094047015655f, \
   -0.00487035299301066f,   -0.0003917403729959771f, 0.0006754494059985568f, \
   -0.00011747678400228192f }

typedef unsigned long long u64t;

__device__ __forceinline__ u64t pk(float lo, float hi) {
    u64t r;
    asm("mov.b64 %0, {%1, %2};"
        : "=l"(r) : "r"(__float_as_uint(lo)), "r"(__float_as_uint(hi)));
    return r;
}
__device__ __forceinline__ void upk(u64t v, float& lo, float& hi) {
    unsigned a, b;
    asm("mov.b64 {%0, %1}, %2;" : "=r"(a), "=r"(b) : "l"(v));
    lo = __uint_as_float(a); hi = __uint_as_float(b);
}
__device__ __forceinline__ u64t fma2(u64t a, u64t b, u64t c) {
    u64t r;
    asm("fma.rn.f32x2 %0, %1, %2, %3;" : "=l"(r) : "l"(a), "l"(b), "l"(c));
    return r;
}

__device__ __forceinline__ float softthr(float v, float thr) {
    float av = fabsf(v) - thr;
    return av > 0.f ? copysignf(av, v) : 0.f;
}

// packed DWT: 4 (a,d) pairs from pairs p[k]=(w[2k],w[2k+1]); uses p[1..11]
__device__ __forceinline__ void dwt4_p(const u64t* p, float* o) {
    const float H[16] = HLIT;
    #pragma unroll
    for (int r = 0; r < 4; r++) {
        u64t a2 = 0ull, d2 = 0ull;
        #pragma unroll
        for (int s = 0; s < 8; s++) {
            a2 = fma2(pk(H[2*s],      H[2*s+1]),  p[r + s], a2);
            d2 = fma2(pk(H[15-2*s],  -H[14-2*s]), p[r + s], d2);
        }
        float al, ah, dl, dh;
        upk(a2, al, ah); upk(d2, dl, dh);
        o[2*r]     = al + ah;
        o[2*r + 1] = dl + dh;
    }
}

// packed IDWT: p[j]=(a[j], d_thresholded[j])
__device__ __forceinline__ void idwt4_p(const u64t* p, float* o) {
    const float H[16] = HLIT;
    #pragma unroll
    for (int pp = 0; pp < 4; pp++) {
        u64t e2 = 0ull, q2 = 0ull;
        #pragma unroll
        for (int s = 0; s < 8; s++) {
            e2 = fma2(pk(H[14-2*s], H[2*s+1]), p[pp + s], e2);
            q2 = fma2(pk(H[15-2*s], -H[2*s]),  p[pp + s], q2);
        }
        float el, eh, ol, oh;
        upk(e2, el, eh); upk(q2, ol, oh);
        o[2*pp]     = el + eh;
        o[2*pp + 1] = ol + oh;
    }
}

// generic DWT pass over smem input (levels 2-4)
__device__ __forceinline__ void dwt_pass(const float* __restrict__ xin, int n,
                                         float* __restrict__ ca_smem,
                                         float* __restrict__ cd_gmem, int nout,
                                         int tid)
{
    for (int base = 4 * tid; base < nout; base += 1024) {
        u64t q[12];
        int lo = 2 * base - 16;
        if (lo >= 0 && lo + 24 <= n) {
            const ulonglong2* p = reinterpret_cast<const ulonglong2*>(xin + lo);
            #pragma unroll
            for (int j = 0; j < 6; j++) { ulonglong2 v = p[j]; q[2*j] = v.x; q[2*j+1] = v.y; }
        } else {
            float w[24];
            #pragma unroll
            for (int j = 0; j < 24; j++) {
                int m = lo + j;
                m = (m < 0) ? (-1 - m) : m;
                m = (m >= n) ? (2 * n - 1 - m) : m;
                w[j] = xin[m];
            }
            #pragma unroll
            for (int j = 0; j < 12; j++) q[j] = pk(w[2*j], w[2*j+1]);
        }
        float o[8];
        dwt4_p(q + 1, o);
        if (base + 4 <= nout) {
            *reinterpret_cast<float4*>(ca_smem + base) = make_float4(o[0], o[2], o[4], o[6]);
            *reinterpret_cast<float4*>(cd_gmem + base) = make_float4(o[1], o[3], o[5], o[7]);
        } else {
            #pragma unroll
            for (int r = 0; r < 4; r++)
                if (base + r < nout) { ca_smem[base + r] = o[2*r]; cd_gmem[base + r] = o[2*r+1]; }
        }
    }
}

__device__ __forceinline__ int refl(int m) {
    m = (m < 0) ? (-1 - m) : m;
    return (m >= LROW) ? (2 * LROW - 1 - m) : m;
}

// ============ K_fwd: level-1 DWT (warp-staged) + median + levels 2-4 ========
__global__ void __launch_bounds__(256, 3)
k_fwd(const float* __restrict__ x, float* __restrict__ d1g,
      float* __restrict__ d2g, float* __restrict__ d3g,
      float* __restrict__ d4g, float* __restrict__ a4g,
      float* __restrict__ thr_out)
{
    extern __shared__ float sm[];
    float* A1 = sm;              // flat 8200
    float* A2 = sm + OFF_HI;     // flat 4108
    float* A3 = sm;              // overlays dead A1

    __shared__ int      s_hist[4][256];
    __shared__ unsigned s_pref;
    __shared__ int      s_rank;

    const int tid = threadIdx.x, lane = tid & 31, warp = tid >> 5;
    const int row = blockIdx.x;
    const float* xin = x + (size_t)row * LROW;
    float* pd1 = d1g + (size_t)row * S1;
    float* pd2 = d2g + (size_t)row * S2;
    float* pd3 = d3g + (size_t)row * S3;
    float* pd4 = d4g + (size_t)row * S4;
    float* pa4 = a4g + (size_t)row * S4;
    float* xw  = sm + OFF_XW + XW_STRIDE * warp;   // 288 floats used

    #pragma unroll
    for (int rr = 0; rr < 4; rr++) s_hist[rr][tid] = 0;
    if (tid == 0) { s_pref = 0u; s_rank = (N1 - 1) / 2; }

    // ---- level 1: per-warp staged, coalesced GMEM, windows from SMEM ----
    float dreg[32];
    #pragma unroll
    for (int c = 0; c < 8; c++) {
        const int B  = 1024 * c + 128 * warp;     // warp's first output this iter
        const int g0 = 2 * B - 16;                // stage [g0, g0+288), 32B aligned
        #pragma unroll
        for (int rr = 0; rr < 3; rr++) {
            int j = lane + 32 * rr;
            if (rr < 2 || lane < 8) {             // 72 float4s total
                int g = g0 + 4 * j;
                float4 v;
                if (g >= 0 && g + 4 <= LROW) {
                    v = *reinterpret_cast<const float4*>(xin + g);
                } else {                           // edge reflect (few lanes only)
                    v = make_float4(xin[refl(g)], xin[refl(g + 1)],
                                    xin[refl(g + 2)], xin[refl(g + 3)]);
                }
                *reinterpret_cast<float4*>(xw + 4 * j) = v;
            }
        }
        __syncwarp();
        // window pairs from staged smem: local offset 8*lane floats
        u64t q[12];
        {
            const ulonglong2* p = reinterpret_cast<const ulonglong2*>(xw + 8 * lane);
            #pragma unroll
            for (int j = 0; j < 6; j++) { ulonglong2 v = p[j]; q[2*j] = v.x; q[2*j+1] = v.y; }
        }
        float o[8];
        dwt4_p(q + 1, o);
        int base = B + 4 * lane;
        *reinterpret_cast<float4*>(A1 + base)  = make_float4(o[0], o[2], o[4], o[6]);
        *reinterpret_cast<float4*>(pd1 + base) = make_float4(o[1], o[3], o[5], o[7]);
        dreg[4*c] = o[1]; dreg[4*c+1] = o[3]; dreg[4*c+2] = o[5]; dreg[4*c+3] = o[7];
        __syncwarp();                              // staging reused next iter
    }
    // tail k = 8192..8198, one output per thread (tids 0-6)
    float dtail = 0.f;
    if (tid < 7) {
        const float H[16] = HLIT;
        int k = 8192 + tid;
        float a = 0.f, d = 0.f;
        #pragma unroll
        for (int t = 0; t < 16; t++) {
            int m = 2 * k + t - 14;
            if (m >= LROW) m = 2 * LROW - 1 - m;
            float xv = xin[m];
            a = fmaf(H[t], xv, a);
            d = fmaf((t & 1) ? -H[15 - t] : H[15 - t], xv, d);
        }
        A1[k] = a; pd1[k] = d; dtail = d;
    }
    __syncthreads();

    // ---- exact median of |d1|: 4-round radix select ----
    for (int b3 = 3; b3 >= 0; --b3) {
        const unsigned pref = s_pref;
        const int rank = s_rank;
        const int sh = b3 * 8;
        int* hist = s_hist[b3];
        #pragma unroll
        for (int j = 0; j < 32; j++) {
            unsigned u = __float_as_uint(fabsf(dreg[j]));
            bool mt = (b3 == 3) || ((u >> (sh + 8)) == pref);
            if (__any_sync(0xffffffffu, mt)) {
                unsigned bin = (u >> sh) & 255u;
                unsigned key = mt ? bin : 256u;
                unsigned grp = __match_any_sync(0xffffffffu, key);
                if (mt && lane == (__ffs(grp) - 1))
                    atomicAdd(&hist[bin], __popc(grp));
            }
        }
        if (tid < 7) {
            unsigned u = __float_as_uint(fabsf(dtail));
            if ((b3 == 3) || ((u >> (sh + 8)) == pref))
                atomicAdd(&hist[(u >> sh) & 255u], 1);
        }
        __syncthreads();
        if (warp == 0) {
            int base = lane * 8;
            int cnt[8], s = 0;
            #pragma unroll
            for (int qq = 0; qq < 8; qq++) { cnt[qq] = hist[base + qq]; s += cnt[qq]; }
            int incl = s;
            #pragma unroll
            for (int o = 1; o < 32; o <<= 1) {
                int t2 = __shfl_up_sync(0xffffffffu, incl, o);
                if (lane >= o) incl += t2;
            }
            int excl = incl - s;
            if (rank >= excl && rank < incl) {
                int acc = excl;
                #pragma unroll
                for (int qq = 0; qq < 8; qq++) {
                    if (rank < acc + cnt[qq]) {
                        s_pref = (pref << 8) | (unsigned)(base + qq);
                        s_rank = rank - acc;
                        break;
                    }
                    acc += cnt[qq];
                }
            }
        }
        __syncthreads();
    }
    if (tid == 0) {
        float med = __uint_as_float(s_pref);
        thr_out[row] = (med / 0.6745f) * 4.4054649f;   // * sqrt(2 ln 16384)
    }

    // ---- levels 2-4 ----
    dwt_pass(A1, N1, A2, pd2, N2, tid);   __syncthreads();
    dwt_pass(A2, N2, A3, pd3, N3, tid);   __syncthreads();   // A3 overlays A1
    {
        for (int base = 4 * tid; base < N4; base += 1024) {
            u64t q[12];
            int lo = 2 * base - 16;
            if (lo >= 0 && lo + 24 <= N3) {
                const ulonglong2* p = reinterpret_cast<const ulonglong2*>(A3 + lo);
                #pragma unroll
                for (int j = 0; j < 6; j++) { ulonglong2 v = p[j]; q[2*j] = v.x; q[2*j+1] = v.y; }
            } else {
                float w[24];
                #pragma unroll
                for (int j = 0; j < 24; j++) {
                    int m = lo + j;
                    m = (m < 0) ? (-1 - m) : m;
                    m = (m >= N3) ? (2 * N3 - 1 - m) : m;
                    w[j] = A3[m];
                }
                #pragma unroll
                for (int j = 0; j < 12; j++) q[j] = pk(w[2*j], w[2*j+1]);
            }
            float o[8];
            dwt4_p(q + 1, o);
            if (base + 4 <= N4) {
                *reinterpret_cast<float4*>(pa4 + base) = make_float4(o[0], o[2], o[4], o[6]);
                *reinterpret_cast<float4*>(pd4 + base) = make_float4(o[1], o[3], o[5], o[7]);
            } else {
                #pragma unroll
                for (int r = 0; r < 4; r++)
                    if (base + r < N4) { pa4[base + r] = o[2*r]; pd4[base + r] = o[2*r+1]; }
            }
        }
    }
}

// ---- IDWT pass (packed); fused soft threshold ----
__device__ __forceinline__ void idwt_pass(const float* __restrict__ ca,
                                          const float* __restrict__ cd,
                                          int n, float thr,
                                          float* __restrict__ rec, int tid)
{
    int plim = n - 7;
    for (int p0 = 4 * tid; p0 < plim; p0 += 1024) {
        u64t p[12];
        if (p0 + 12 <= n) {
            #pragma unroll
            for (int j = 0; j < 3; j++) {
                float4 va = *reinterpret_cast<const float4*>(ca + p0 + 4 * j);
                float4 vd = *reinterpret_cast<const float4*>(cd + p0 + 4 * j);
                p[4*j]   = pk(va.x, softthr(vd.x, thr));
                p[4*j+1] = pk(va.y, softthr(vd.y, thr));
                p[4*j+2] = pk(va.z, softthr(vd.z, thr));
                p[4*j+3] = pk(va.w, softthr(vd.w, thr));
            }
        } else {
            #pragma unroll
            for (int j = 0; j < 12; j++) {
                int q = p0 + j; if (q > n - 1) q = n - 1;
                p[j] = pk(ca[q], softthr(cd[q], thr));
            }
        }
        float o[8];
        idwt4_p(p, o);
        if (p0 + 4 <= plim) {
            *reinterpret_cast<float4*>(rec + 2 * p0)     = make_float4(o[0], o[1], o[2], o[3]);
            *reinterpret_cast<float4*>(rec + 2 * p0 + 4) = make_float4(o[4], o[5], o[6], o[7]);
        } else {
            #pragma unroll
            for (int pp = 0; pp < 4; pp++)
                if (p0 + pp < plim) {
                    rec[2 * (p0 + pp)]     = o[2*pp];
                    rec[2 * (p0 + pp) + 1] = o[2*pp+1];
                }
        }
    }
}

// ============ K_inv: IDWT 4 -> 3 -> 2 -> 1, final level streams to out ======
__global__ void __launch_bounds__(256, 4)
k_inv(const float* __restrict__ a4g, const float* __restrict__ d4g,
      const float* __restrict__ d3g, const float* __restrict__ d2g,
      const float* __restrict__ d1g, const float* __restrict__ thr_arr,
      float* __restrict__ out)
{
    extern __shared__ float sm[];
    float* REC = sm;
    float* R4  = sm;
    float* R3  = sm + OFF_HI;

    const int tid = threadIdx.x;
    const int row = blockIdx.x;
    const float thr = __ldg(thr_arr + row);
    const float* pa4 = a4g + (size_t)row * S4;
    const float* pd4 = d4g + (size_t)row * S4;
    const float* pd3 = d3g + (size_t)row * S3;
    const float* pd2 = d2g + (size_t)row * S2;
    const float* pd1 = d1g + (size_t)row * S1;
    float* orow = out + (size_t)row * LROW;

    idwt_pass(pa4, pd4, N4, thr, R4, tid);   __syncthreads();
    idwt_pass(R4,  pd3, N3, thr, R3, tid);   __syncthreads();
    idwt_pass(R3,  pd2, N2, thr, REC, tid);  __syncthreads();
    idwt_pass(REC, pd1, N1, thr, orow, tid);
}

extern "C" void kernel_launch(void* const* d_in, const int* in_sizes, int n_in,
                              void* d_out, int out_size)
{
    const float* x = (const float*)d_in[0];
    float* out = (float*)d_out;
    int rows = in_sizes[0] / LROW;   // 2048

    float *d1, *d2, *d3, *d4, *a4, *thr;
    cudaGetSymbolAddress((void**)&d1, g_d1);
    cudaGetSymbolAddress((void**)&d2, g_d2);
    cudaGetSymbolAddress((void**)&d3, g_d3);
    cudaGetSymbolAddress((void**)&d4, g_d4);
    cudaGetSymbolAddress((void**)&a4, g_a4);
    cudaGetSymbolAddress((void**)&thr, g_thr);

    cudaFuncSetAttribute(k_fwd, cudaFuncAttributeMaxDynamicSharedMemorySize, SM_BYTES_FWD);
    cudaFuncSetAttribute(k_inv, cudaFuncAttributeMaxDynamicSharedMemorySize, SM_BYTES_INV);

    k_fwd<<<rows, 256, SM_BYTES_FWD>>>(x, d1, d2, d3, d4, a4, thr);
    k_inv<<<rows, 256, SM_BYTES_INV>>>(a4, d4, d3, d2, d1, thr, out);
}

// round 16
// speedup vs baseline: 1.0781x; 1.0781x over previous
#include <cuda_runtime.h>

#define LROW 16384
#define N1 8199
#define N2 4107
#define N3 2061
#define N4 1038
#define ROWS_MAX 2048

#define S1 8200
#define S2 4112
#define S3 2064
#define S4 1040

__device__ float g_d1[(size_t)ROWS_MAX * S1];
__device__ float g_d2[(size_t)ROWS_MAX * S2];
__device__ float g_d3[(size_t)ROWS_MAX * S3];
__device__ float g_d4[(size_t)ROWS_MAX * S4];
__device__ float g_a4[(size_t)ROWS_MAX * S4];

// smem: fwd: A1[0,8208) A2[8208,12320), A3 overlays A1.
//       inv: REC[0,8208) R3[8208,12320), R4 overlays REC.
#define SM_FLOATS 12320
#define SM_BYTES  (SM_FLOATS * 4)
#define OFF_HI    8208

#define HLIT { \
    0.05441584224308161f,    0.3128715909144659f,    0.6756307362980128f, \
    0.5853546836548691f,    -0.015829105256023893f, -0.2840155429624281f, \
    0.00047248457399797254f, 0.128747426620186f,    -0.01736930100202211f, \
   -0.04408825393106472f,    0.013981027917015516f,  0.008746094047015655f, \
   -0.00487035299301066f,   -0.0003917403729959771f, 0.0006754494059985568f, \
   -0.00011747678400228192f }

typedef unsigned long long u64t;

__device__ __forceinline__ u64t pk(float lo, float hi) {
    u64t r;
    asm("mov.b64 %0, {%1, %2};"
        : "=l"(r) : "r"(__float_as_uint(lo)), "r"(__float_as_uint(hi)));
    return r;
}
__device__ __forceinline__ void upk(u64t v, float& lo, float& hi) {
    unsigned a, b;
    asm("mov.b64 {%0, %1}, %2;" : "=r"(a), "=r"(b) : "l"(v));
    lo = __uint_as_float(a); hi = __uint_as_float(b);
}
__device__ __forceinline__ u64t fma2(u64t a, u64t b, u64t c) {
    u64t r;
    asm("fma.rn.f32x2 %0, %1, %2, %3;" : "=l"(r) : "l"(a), "l"(b), "l"(c));
    return r;
}

__device__ __forceinline__ float softthr(float v, float thr) {
    float av = fabsf(v) - thr;
    return av > 0.f ? copysignf(av, v) : 0.f;
}

// packed DWT: 4 (a,d) pairs from pairs p[k]=(w[2k],w[2k+1]); uses p[1..11]
__device__ __forceinline__ void dwt4_p(const u64t* p, float* o) {
    const float H[16] = HLIT;
    #pragma unroll
    for (int r = 0; r < 4; r++) {
        u64t a2 = 0ull, d2 = 0ull;
        #pragma unroll
        for (int s = 0; s < 8; s++) {
            a2 = fma2(pk(H[2*s],      H[2*s+1]),  p[r + s], a2);
            d2 = fma2(pk(H[15-2*s],  -H[14-2*s]), p[r + s], d2);
        }
        float al, ah, dl, dh;
        upk(a2, al, ah); upk(d2, dl, dh);
        o[2*r]     = al + ah;
        o[2*r + 1] = dl + dh;
    }
}

// packed IDWT: p[j]=(a[j], d_thresholded[j])
__device__ __forceinline__ void idwt4_p(const u64t* p, float* o) {
    const float H[16] = HLIT;
    #pragma unroll
    for (int pp = 0; pp < 4; pp++) {
        u64t e2 = 0ull, q2 = 0ull;
        #pragma unroll
        for (int s = 0; s < 8; s++) {
            e2 = fma2(pk(H[14-2*s], H[2*s+1]), p[pp + s], e2);
            q2 = fma2(pk(H[15-2*s], -H[2*s]),  p[pp + s], q2);
        }
        float el, eh, ol, oh;
        upk(e2, el, eh); upk(q2, ol, oh);
        o[2*pp]     = el + eh;
        o[2*pp + 1] = ol + oh;
    }
}

// generic DWT pass
__device__ __forceinline__ void dwt_pass(const float* __restrict__ xin, int n,
                                         float* __restrict__ ca_smem,
                                         float* __restrict__ cd_gmem, int nout,
                                         int tid)
{
    for (int base = 4 * tid; base < nout; base += 1024) {
        u64t q[12];
        int lo = 2 * base - 16;
        if (lo >= 0 && lo + 24 <= n) {
            const ulonglong2* p = reinterpret_cast<const ulonglong2*>(xin + lo);
            #pragma unroll
            for (int j = 0; j < 6; j++) { ulonglong2 v = p[j]; q[2*j] = v.x; q[2*j+1] = v.y; }
        } else {
            float w[24];
            #pragma unroll
            for (int j = 0; j < 24; j++) {
                int m = lo + j;
                m = (m < 0) ? (-1 - m) : m;
                m = (m >= n) ? (2 * n - 1 - m) : m;
                w[j] = xin[m];
            }
            #pragma unroll
            for (int j = 0; j < 12; j++) q[j] = pk(w[2*j], w[2*j+1]);
        }
        float o[8];
        dwt4_p(q + 1, o);
        if (base + 4 <= nout) {
            *reinterpret_cast<float4*>(ca_smem + base) = make_float4(o[0], o[2], o[4], o[6]);
            *reinterpret_cast<float4*>(cd_gmem + base) = make_float4(o[1], o[3], o[5], o[7]);
        } else {
            #pragma unroll
            for (int r = 0; r < 4; r++)
                if (base + r < nout) { ca_smem[base + r] = o[2*r]; cd_gmem[base + r] = o[2*r+1]; }
        }
    }
}

// ============ K_fwd: pure DWT levels 1-4 (no median) ========================
__global__ void __launch_bounds__(256, 4)
k_fwd(const float* __restrict__ x, float* __restrict__ d1g,
      float* __restrict__ d2g, float* __restrict__ d3g,
      float* __restrict__ d4g, float* __restrict__ a4g)
{
    extern __shared__ float sm[];
    float* A1 = sm;              // flat 8200
    float* A2 = sm + OFF_HI;     // flat 4108
    float* A3 = sm;              // overlays dead A1

    const int tid = threadIdx.x;
    const int row = blockIdx.x;
    const float* xin = x + (size_t)row * LROW;
    float* pd1 = d1g + (size_t)row * S1;
    float* pd2 = d2g + (size_t)row * S2;
    float* pd3 = d3g + (size_t)row * S3;
    float* pd4 = d4g + (size_t)row * S4;
    float* pa4 = a4g + (size_t)row * S4;

    // ---- level 1: x -> A1 smem + d1 global ----
    #pragma unroll
    for (int c = 0; c < 8; c++) {
        int base = 1024 * c + 4 * tid;       // < 8192
        int lo = 2 * base - 16;              // lo+24 <= 16384 always
        u64t q[12];
        if (lo >= 0) {
            const ulonglong2* p = reinterpret_cast<const ulonglong2*>(xin + lo);
            #pragma unroll
            for (int j = 0; j < 6; j++) { ulonglong2 v = p[j]; q[2*j] = v.x; q[2*j+1] = v.y; }
        } else {                              // c==0, tid<2 only (left reflect)
            float w[24];
            #pragma unroll
            for (int j = 0; j < 24; j++) {
                int m = lo + j;
                m = (m < 0) ? (-1 - m) : m;
                w[j] = xin[m];
            }
            #pragma unroll
            for (int j = 0; j < 12; j++) q[j] = pk(w[2*j], w[2*j+1]);
        }
        float o[8];
        dwt4_p(q + 1, o);
        *reinterpret_cast<float4*>(A1 + base)  = make_float4(o[0], o[2], o[4], o[6]);
        *reinterpret_cast<float4*>(pd1 + base) = make_float4(o[1], o[3], o[5], o[7]);
    }
    if (tid < 7) {                            // tail k = 8192..8198, distributed
        const float H[16] = HLIT;
        int k = 8192 + tid;
        float a = 0.f, d = 0.f;
        #pragma unroll
        for (int t = 0; t < 16; t++) {
            int m = 2 * k + t - 14;
            if (m >= LROW) m = 2 * LROW - 1 - m;
            float xv = xin[m];
            a = fmaf(H[t], xv, a);
            d = fmaf((t & 1) ? -H[15 - t] : H[15 - t], xv, d);
        }
        A1[k] = a; pd1[k] = d;
    }
    __syncthreads();

    // ---- levels 2-4 ----
    dwt_pass(A1, N1, A2, pd2, N2, tid);   __syncthreads();
    dwt_pass(A2, N2, A3, pd3, N3, tid);   __syncthreads();   // A3 overlays A1
    {
        for (int base = 4 * tid; base < N4; base += 1024) {
            u64t q[12];
            int lo = 2 * base - 16;
            if (lo >= 0 && lo + 24 <= N3) {
                const ulonglong2* p = reinterpret_cast<const ulonglong2*>(A3 + lo);
                #pragma unroll
                for (int j = 0; j < 6; j++) { ulonglong2 v = p[j]; q[2*j] = v.x; q[2*j+1] = v.y; }
            } else {
                float w[24];
                #pragma unroll
                for (int j = 0; j < 24; j++) {
                    int m = lo + j;
                    m = (m < 0) ? (-1 - m) : m;
                    m = (m >= N3) ? (2 * N3 - 1 - m) : m;
                    w[j] = A3[m];
                }
                #pragma unroll
                for (int j = 0; j < 12; j++) q[j] = pk(w[2*j], w[2*j+1]);
            }
            float o[8];
            dwt4_p(q + 1, o);
            if (base + 4 <= N4) {
                *reinterpret_cast<float4*>(pa4 + base) = make_float4(o[0], o[2], o[4], o[6]);
                *reinterpret_cast<float4*>(pd4 + base) = make_float4(o[1], o[3], o[5], o[7]);
            } else {
                #pragma unroll
                for (int r = 0; r < 4; r++)
                    if (base + r < N4) { pa4[base + r] = o[2*r]; pd4[base + r] = o[2*r+1]; }
            }
        }
    }
}

// ---- IDWT pass (packed); fused soft threshold ----
__device__ __forceinline__ void idwt_pass(const float* __restrict__ ca,
                                          const float* __restrict__ cd,
                                          int n, float thr,
                                          float* __restrict__ rec, int tid)
{
    int plim = n - 7;
    for (int p0 = 4 * tid; p0 < plim; p0 += 1024) {
        u64t p[12];
        if (p0 + 12 <= n) {
            #pragma unroll
            for (int j = 0; j < 3; j++) {
                float4 va = *reinterpret_cast<const float4*>(ca + p0 + 4 * j);
                float4 vd = *reinterpret_cast<const float4*>(cd + p0 + 4 * j);
                p[4*j]   = pk(va.x, softthr(vd.x, thr));
                p[4*j+1] = pk(va.y, softthr(vd.y, thr));
                p[4*j+2] = pk(va.z, softthr(vd.z, thr));
                p[4*j+3] = pk(va.w, softthr(vd.w, thr));
            }
        } else {
            #pragma unroll
            for (int j = 0; j < 12; j++) {
                int q = p0 + j; if (q > n - 1) q = n - 1;
                p[j] = pk(ca[q], softthr(cd[q], thr));
            }
        }
        float o[8];
        idwt4_p(p, o);
        if (p0 + 4 <= plim) {
            *reinterpret_cast<float4*>(rec + 2 * p0)     = make_float4(o[0], o[1], o[2], o[3]);
            *reinterpret_cast<float4*>(rec + 2 * p0 + 4) = make_float4(o[4], o[5], o[6], o[7]);
        } else {
            #pragma unroll
            for (int pp = 0; pp < 4; pp++)
                if (p0 + pp < plim) {
                    rec[2 * (p0 + pp)]     = o[2*pp];
                    rec[2 * (p0 + pp) + 1] = o[2*pp+1];
                }
        }
    }
}

// ============ K_inv: median(d1) then IDWT 4 -> 3 -> 2 -> 1 ==================
__global__ void __launch_bounds__(256, 4)
k_inv(const float* __restrict__ a4g, const float* __restrict__ d4g,
      const float* __restrict__ d3g, const float* __restrict__ d2g,
      const float* __restrict__ d1g, float* __restrict__ out)
{
    extern __shared__ float sm[];
    float* REC = sm;             // flat 8200
    float* R4  = sm;             // overlays REC
    float* R3  = sm + OFF_HI;    // flat 4108

    __shared__ int      s_hist[4][256];
    __shared__ unsigned s_pref;
    __shared__ int      s_rank;
    __shared__ float    s_thr;

    const int tid = threadIdx.x, lane = tid & 31, warp = tid >> 5;
    const int row = blockIdx.x;
    const float* pa4 = a4g + (size_t)row * S4;
    const float* pd4 = d4g + (size_t)row * S4;
    const float* pd3 = d3g + (size_t)row * S3;
    const float* pd2 = d2g + (size_t)row * S2;
    const float* pd1 = d1g + (size_t)row * S1;
    float* orow = out + (size_t)row * LROW;

    #pragma unroll
    for (int rr = 0; rr < 4; rr++) s_hist[rr][tid] = 0;
    if (tid == 0) { s_pref = 0u; s_rank = (N1 - 1) / 2; }

    // ---- load d1 into registers (coalesced, high MLP) ----
    float dreg[32];
    #pragma unroll
    for (int c = 0; c < 8; c++) {
        float4 v = *reinterpret_cast<const float4*>(pd1 + 1024 * c + 4 * tid);
        dreg[4*c] = v.x; dreg[4*c+1] = v.y; dreg[4*c+2] = v.z; dreg[4*c+3] = v.w;
    }
    const float dtail = (tid < 7) ? pd1[8192 + tid] : 0.f;
    __syncthreads();

    // ---- exact median of |d1|: 4-round radix select on fp32 bits ----
    for (int b3 = 3; b3 >= 0; --b3) {
        const unsigned pref = s_pref;
        const int rank = s_rank;
        const int sh = b3 * 8;
        int* hist = s_hist[b3];
        #pragma unroll
        for (int j = 0; j < 32; j++) {
            unsigned u = __float_as_uint(fabsf(dreg[j]));
            bool mt = (b3 == 3) || ((u >> (sh + 8)) == pref);
            if (__any_sync(0xffffffffu, mt)) {
                unsigned bin = (u >> sh) & 255u;
                unsigned key = mt ? bin : 256u;
                unsigned grp = __match_any_sync(0xffffffffu, key);
                if (mt && lane == (__ffs(grp) - 1))
                    atomicAdd(&hist[bin], __popc(grp));
            }
        }
        if (tid < 7) {
            unsigned u = __float_as_uint(fabsf(dtail));
            if ((b3 == 3) || ((u >> (sh + 8)) == pref))
                atomicAdd(&hist[(u >> sh) & 255u], 1);
        }
        __syncthreads();
        if (warp == 0) {
            int base = lane * 8;
            int cnt[8], s = 0;
            #pragma unroll
            for (int qq = 0; qq < 8; qq++) { cnt[qq] = hist[base + qq]; s += cnt[qq]; }
            int incl = s;
            #pragma unroll
            for (int o = 1; o < 32; o <<= 1) {
                int t2 = __shfl_up_sync(0xffffffffu, incl, o);
                if (lane >= o) incl += t2;
            }
            int excl = incl - s;
            if (rank >= excl && rank < incl) {
                int acc = excl;
                #pragma unroll
                for (int qq = 0; qq < 8; qq++) {
                    if (rank < acc + cnt[qq]) {
                        s_pref = (pref << 8) | (unsigned)(base + qq);
                        s_rank = rank - acc;
                        break;
                    }
                    acc += cnt[qq];
                }
            }
        }
        __syncthreads();
    }
    if (tid == 0) {
        float med = __uint_as_float(s_pref);
        s_thr = (med / 0.6745f) * 4.4054649f;   // * sqrt(2 ln 16384)
    }
    __syncthreads();
    const float thr = s_thr;

    // ---- IDWT cascade ----
    idwt_pass(pa4, pd4, N4, thr, R4, tid);   __syncthreads();  // R4 flat 2062
    idwt_pass(R4,  pd3, N3, thr, R3, tid);   __syncthreads();  // R3 flat 4108
    idwt_pass(R3,  pd2, N2, thr, REC, tid);  __syncthreads();  // REC flat 8200
    idwt_pass(REC, pd1, N1, thr, orow, tid);                   // 16384 -> out
}

extern "C" void kernel_launch(void* const* d_in, const int* in_sizes, int n_in,
                              void* d_out, int out_size)
{
    const float* x = (const float*)d_in[0];
    float* out = (float*)d_out;
    int rows = in_sizes[0] / LROW;   // 2048

    float *d1, *d2, *d3, *d4, *a4;
    cudaGetSymbolAddress((void**)&d1, g_d1);
    cudaGetSymbolAddress((void**)&d2, g_d2);
    cudaGetSymbolAddress((void**)&d3, g_d3);
    cudaGetSymbolAddress((void**)&d4, g_d4);
    cudaGetSymbolAddress((void**)&a4, g_a4);

    cudaFuncSetAttribute(k_fwd, cudaFuncAttributeMaxDynamicSharedMemorySize, SM_BYTES);
    cudaFuncSetAttribute(k_inv, cudaFuncAttributeMaxDynamicSharedMemorySize, SM_BYTES);

    k_fwd<<<rows, 256, SM_BYTES>>>(x, d1, d2, d3, d4, a4);
    k_inv<<<rows, 256, SM_BYTES>>>(a4, d4, d3, d2, d1, out);
}